// round 1
// baseline (speedup 1.0000x reference)
#include <cuda_runtime.h>

// Problem constants
#define BB   32          // batch
#define HH   32          // heads
#define DD   128         // head dim
#define HID  4096
#define QKV3 12288       // 3*HID
#define NBLK 16          // blocks per sequence
#define BSZ  64          // block size (tokens per cache block)
#define KSPLIT 4
#define KCH  (HID / KSPLIT)   // 1024 k per split
#define KC   128              // smem-staged k chunk

// ---------------- scratch (__device__ globals; no allocation allowed) ----------------
__device__ float g_qkv_part[KSPLIT][BB][QKV3];  // split-K partials (6.3 MB)
__device__ float g_q [BB * HH * DD];            // rotated q
__device__ float g_kn[BB * HH * DD];            // rotated new k (not written to cache -> inputs stay const)
__device__ float g_vn[BB * HH * DD];            // new v
__device__ float g_attn[BB * HID];              // attention output pre-projection

// ---------------- packed f32x2 helpers ----------------
__device__ __forceinline__ unsigned long long pack2(float x) {
    unsigned long long r; unsigned u = __float_as_uint(x);
    asm("mov.b64 %0, {%1, %1};" : "=l"(r) : "r"(u));
    return r;
}
__device__ __forceinline__ unsigned long long pack2(float x, float y) {
    unsigned long long r;
    asm("mov.b64 %0, {%1, %2};" : "=l"(r) : "r"(__float_as_uint(x)), "r"(__float_as_uint(y)));
    return r;
}
__device__ __forceinline__ void ffma2(unsigned long long& a, unsigned long long x, unsigned long long y) {
    asm("fma.rn.f32x2 %0, %1, %2, %0;" : "+l"(a) : "l"(x), "l"(y));
}
__device__ __forceinline__ float2 unpack2(unsigned long long v) {
    unsigned lo, hi;
    asm("mov.b64 {%0, %1}, %2;" : "=r"(lo), "=r"(hi) : "l"(v));
    return make_float2(__uint_as_float(lo), __uint_as_float(hi));
}

// ---------------- Kernel 1: QKV GEMM, split-K, f32x2 FMA ----------------
// qkv[b][j] = sum_k hidden[b][k] * W_pack[k][j]
// grid (QKV3/128, KSPLIT), 128 threads; thread owns column j = bx*128+tid,
// accumulates all 32 batches as 16 packed f32x2 registers.
__global__ __launch_bounds__(128) void qkv_kernel(const float* __restrict__ hs,
                                                  const float* __restrict__ W) {
    const int col   = blockIdx.x * 128 + threadIdx.x;
    const int split = blockIdx.y;
    const int k0b   = split * KCH;

    __shared__ unsigned long long hs2[16][KC];  // [batch-pair][k] packed hidden

    unsigned long long acc[16];
#pragma unroll
    for (int i = 0; i < 16; i++) acc[i] = 0ull;

    for (int kc = 0; kc < KCH; kc += KC) {
        __syncthreads();
        {
            const int k = k0b + kc + threadIdx.x;
#pragma unroll
            for (int j = 0; j < 16; j++)
                hs2[j][threadIdx.x] = pack2(hs[(2 * j) * HID + k], hs[(2 * j + 1) * HID + k]);
        }
        __syncthreads();

        const float* wp = W + (size_t)(k0b + kc) * QKV3 + col;
#pragma unroll 4
        for (int kk = 0; kk < KC; kk++) {
            unsigned long long w2 = pack2(wp[(size_t)kk * QKV3]);
#pragma unroll
            for (int b2 = 0; b2 < 16; b2++) ffma2(acc[b2], w2, hs2[b2][kk]);
        }
    }

#pragma unroll
    for (int b2 = 0; b2 < 16; b2++) {
        float2 v = unpack2(acc[b2]);
        g_qkv_part[split][2 * b2][col]     = v.x;
        g_qkv_part[split][2 * b2 + 1][col] = v.y;
    }
}

// ---------------- Kernel 2: split-K reduce + RoPE ----------------
// grid (B, 96): head 0..31 = q heads, 32..63 = k heads, 64..95 = v heads.
// 64 threads; thread d handles the rotary pair (d, d+64).
__global__ __launch_bounds__(64) void rope_kernel(const int* __restrict__ hist) {
    const int b = blockIdx.x, head = blockIdx.y, d = threadIdx.x;

    int col;
    if (head < 32)      col = head * DD + d;
    else if (head < 64) col = HID + (head - 32) * DD + d;
    else                col = 2 * HID + (head - 64) * DD + d;

    float x1 = 0.f, x2 = 0.f;
#pragma unroll
    for (int s = 0; s < KSPLIT; s++) {
        x1 += g_qkv_part[s][b][col];
        x2 += g_qkv_part[s][b][col + 64];
    }

    float lo, hi;
    if (head < 64) {
        const float pos = (float)hist[b];
        // inv_freq = 10000^(-2d/128) ; log2(10000) = 13.287712379549449
        const float inv = exp2f(-(float)(2 * d) * (13.287712379549449f / 128.f));
        const float ang = pos * inv;
        const float c = cosf(ang), sn = sinf(ang);
        lo = x1 * c - x2 * sn;   // rot lower half = -x2
        hi = x2 * c + x1 * sn;   // rot upper half = +x1
    } else {
        lo = x1; hi = x2;
    }

    if (head < 32) {
        g_q[(b * HH + head) * DD + d]      = lo;
        g_q[(b * HH + head) * DD + d + 64] = hi;
    } else if (head < 64) {
        const int h = head - 32;
        g_kn[(b * HH + h) * DD + d]      = lo;
        g_kn[(b * HH + h) * DD + d + 64] = hi;
    } else {
        const int h = head - 64;
        g_vn[(b * HH + h) * DD + d]      = lo;
        g_vn[(b * HH + h) * DD + d + 64] = hi;
    }
}

// ---------------- Kernel 3: paged decode attention (flash-style, 1 block per (b,h)) ----------------
// 8 warps, warp w handles s = w, w+8, ... ; s == hist[b] is served from g_kn/g_vn
// (the reference's cache write target) so input caches are never mutated.
__global__ __launch_bounds__(256) void attn_kernel(const float* __restrict__ kcache,
                                                   const float* __restrict__ vcache,
                                                   const int* __restrict__ hist,
                                                   const int* __restrict__ bo) {
    const int b = blockIdx.x, h = blockIdx.y;
    const int tid = threadIdx.x, w = tid >> 5, lane = tid & 31;

    __shared__ float sm_m[8], sm_l[8];
    __shared__ float sm_acc[8][DD];
    __shared__ int   sm_blk[NBLK];

    if (tid < NBLK) sm_blk[tid] = bo[b * NBLK + tid];
    const float4 q4 = reinterpret_cast<const float4*>(g_q + (size_t)(b * HH + h) * DD)[lane];
    const int n = hist[b] + 1;   // valid positions: s in [0, hist]
    __syncthreads();

    float m = -1e30f, l = 0.f;
    float4 acc = make_float4(0.f, 0.f, 0.f, 0.f);

    for (int s = w; s < n; s += 8) {
        const float4 *kp, *vp;
        if (s == n - 1) {
            kp = reinterpret_cast<const float4*>(g_kn + (size_t)(b * HH + h) * DD);
            vp = reinterpret_cast<const float4*>(g_vn + (size_t)(b * HH + h) * DD);
        } else {
            const size_t base = ((((size_t)sm_blk[s >> 6]) * BSZ + (s & 63)) * HH + h) * DD;
            kp = reinterpret_cast<const float4*>(kcache + base);
            vp = reinterpret_cast<const float4*>(vcache + base);
        }
        const float4 kv = kp[lane];
        float dsum = q4.x * kv.x + q4.y * kv.y + q4.z * kv.z + q4.w * kv.w;
#pragma unroll
        for (int o = 16; o; o >>= 1) dsum += __shfl_xor_sync(0xffffffffu, dsum, o);
        const float score = dsum * 0.08838834764831845f;  // 1/sqrt(128)

        const float4 vv = vp[lane];
        const float mn = fmaxf(m, score);
        const float cf = __expf(m - mn);
        const float p  = __expf(score - mn);
        l = l * cf + p;
        acc.x = acc.x * cf + p * vv.x;
        acc.y = acc.y * cf + p * vv.y;
        acc.z = acc.z * cf + p * vv.z;
        acc.w = acc.w * cf + p * vv.w;
        m = mn;
    }

    if (lane == 0) { sm_m[w] = m; sm_l[w] = l; }
    reinterpret_cast<float4*>(sm_acc[w])[lane] = acc;
    __syncthreads();

    if (tid < DD) {
        float M = -1e30f;
#pragma unroll
        for (int i = 0; i < 8; i++) M = fmaxf(M, sm_m[i]);
        float L = 0.f, o = 0.f;
#pragma unroll
        for (int i = 0; i < 8; i++) {
            const float f = __expf(sm_m[i] - M);
            L += f * sm_l[i];
            o += f * sm_acc[i][tid];
        }
        g_attn[b * HID + h * DD + tid] = o / L;
    }
}

// ---------------- Kernel 4: output projection out = attn @ Wo^T ----------------
// out[b][j] = sum_k attn[b][k] * Wo[j][k].  Warp owns 2 output columns, lanes split k,
// batches packed in f32x2. grid = 256 blocks (16 cols each), 256 threads.
__global__ __launch_bounds__(256) void oproj_kernel(const float* __restrict__ Wo,
                                                    float* __restrict__ out) {
    const int tid = threadIdx.x, w = tid >> 5, lane = tid & 31;
    const int j0 = blockIdx.x * 16 + w * 2;

    __shared__ unsigned long long a2[16][256];  // [batch-pair][k-chunk] packed attn

    unsigned long long acc[2][16];
#pragma unroll
    for (int jj = 0; jj < 2; jj++)
#pragma unroll
        for (int i = 0; i < 16; i++) acc[jj][i] = 0ull;

    for (int k0 = 0; k0 < HID; k0 += 256) {
        __syncthreads();
#pragma unroll
        for (int j = 0; j < 16; j++)
            a2[j][tid] = pack2(g_attn[(2 * j) * HID + k0 + tid],
                               g_attn[(2 * j + 1) * HID + k0 + tid]);
        __syncthreads();

        for (int kk = lane; kk < 256; kk += 32) {
            unsigned long long hv[16];
#pragma unroll
            for (int b2 = 0; b2 < 16; b2++) hv[b2] = a2[b2][kk];
#pragma unroll
            for (int jj = 0; jj < 2; jj++) {
                const unsigned long long w2 = pack2(Wo[(size_t)(j0 + jj) * HID + k0 + kk]);
#pragma unroll
                for (int b2 = 0; b2 < 16; b2++) ffma2(acc[jj][b2], w2, hv[b2]);
            }
        }
    }

#pragma unroll
    for (int jj = 0; jj < 2; jj++) {
#pragma unroll
        for (int b2 = 0; b2 < 16; b2++) {
            float2 v = unpack2(acc[jj][b2]);
#pragma unroll
            for (int o = 16; o; o >>= 1) {
                v.x += __shfl_xor_sync(0xffffffffu, v.x, o);
                v.y += __shfl_xor_sync(0xffffffffu, v.y, o);
            }
            if (lane == 0) {
                out[(2 * b2) * HID + j0 + jj]     = v.x;
                out[(2 * b2 + 1) * HID + j0 + jj] = v.y;
            }
        }
    }
}

// ---------------- launch ----------------
extern "C" void kernel_launch(void* const* d_in, const int* in_sizes, int n_in,
                              void* d_out, int out_size) {
    const float* hs     = (const float*)d_in[0];  // hidden_states [32,4096]
    const float* Wpack  = (const float*)d_in[1];  // W_pack [4096,12288]
    const float* Wo     = (const float*)d_in[2];  // o_proj_weight [4096,4096]
    const float* kcache = (const float*)d_in[3];  // [512,64,32,128]
    const float* vcache = (const float*)d_in[4];
    const int*   hist   = (const int*)d_in[5];    // [32]
    const int*   bo     = (const int*)d_in[6];    // [32,16]
    float* out = (float*)d_out;                   // [32,4096] fp32

    qkv_kernel <<<dim3(QKV3 / 128, KSPLIT), 128>>>(hs, Wpack);
    rope_kernel<<<dim3(BB, 96), 64>>>(hist);
    attn_kernel<<<dim3(BB, HH), 256>>>(kcache, vcache, hist, bo);
    oproj_kernel<<<HID / 16, 256>>>(Wo, out);
}

// round 2
// speedup vs baseline: 1.1835x; 1.1835x over previous
#include <cuda_runtime.h>

// Problem constants
#define BB   32          // batch
#define HH   32          // heads
#define DD   128         // head dim
#define HID  4096
#define QKV3 12288       // 3*HID
#define NBLK 16          // blocks per sequence
#define BSZ  64          // cache block size

#define KSPLIT_Q 16
#define KCH_Q    256     // 4096/16
#define KSPLIT_O 4

typedef unsigned long long ull;

// ---------------- scratch (__device__ globals) ----------------
__device__ float g_qkv_part[KSPLIT_Q][BB][QKV3];  // 25.2 MB split-K partials
__device__ float g_q [BB * HH * DD];
__device__ float g_kn[BB * HH * DD];
__device__ float g_vn[BB * HH * DD];
__device__ float g_attn[BB * HID];
__device__ float g_o_part[KSPLIT_O][BB][HID];     // 2.1 MB

// ---------------- packed f32x2 helpers ----------------
__device__ __forceinline__ ull pack2(float x) {
    ull r; unsigned u = __float_as_uint(x);
    asm("mov.b64 %0, {%1, %1};" : "=l"(r) : "r"(u));
    return r;
}
__device__ __forceinline__ ull pack2(float x, float y) {
    ull r;
    asm("mov.b64 %0, {%1, %2};" : "=l"(r) : "r"(__float_as_uint(x)), "r"(__float_as_uint(y)));
    return r;
}
__device__ __forceinline__ void ffma2(ull& a, ull x, ull y) {
    asm("fma.rn.f32x2 %0, %1, %2, %0;" : "+l"(a) : "l"(x), "l"(y));
}
__device__ __forceinline__ float2 unpack2(ull v) {
    unsigned lo, hi;
    asm("mov.b64 {%0, %1}, %2;" : "=r"(lo), "=r"(hi) : "l"(v));
    return make_float2(__uint_as_float(lo), __uint_as_float(hi));
}

// ---------------- Kernel 1: QKV GEMM ----------------
// grid (24 colblocks, 16 ksplits), 128 threads.
// Thread owns 4 consecutive columns x all 32 batches (16 f32x2 pairs).
// hidden slice staged in smem pre-packed as batch-pair f32x2; W streamed with
// 2-deep float4 prefetch. Per k: 1 LDG.128 + 4 dup-movs + 16 LDS.64 + 64 FFMA2.
__global__ __launch_bounds__(128, 2) void qkv_kernel(const float* __restrict__ hs,
                                                     const float* __restrict__ W) {
    const int tid  = threadIdx.x;
    const int col0 = blockIdx.x * 512 + tid * 4;
    const int k0   = blockIdx.y * KCH_Q;

    __shared__ ull hs2[16][KCH_Q];   // 32 KB: [batch-pair][k]
    for (int idx = tid; idx < 16 * KCH_Q; idx += 128) {
        const int bp = idx >> 8;            // KCH_Q == 256
        const int kk = idx & (KCH_Q - 1);
        hs2[bp][kk] = pack2(hs[(2 * bp) * HID + k0 + kk],
                            hs[(2 * bp + 1) * HID + k0 + kk]);
    }
    __syncthreads();

    ull acc[16][4];
#pragma unroll
    for (int i = 0; i < 16; i++) { acc[i][0] = acc[i][1] = acc[i][2] = acc[i][3] = 0ull; }

    const float4* wp = reinterpret_cast<const float4*>(W + (size_t)k0 * QKV3 + col0);
    const size_t wstride = QKV3 / 4;

    float4 wa = wp[0];
    float4 wb = wp[wstride];
    for (int kk = 0; kk < KCH_Q; kk++) {
        float4 wn = wa;
        if (kk + 2 < KCH_Q) wn = wp[(size_t)(kk + 2) * wstride];
        const ull w0 = pack2(wa.x), w1 = pack2(wa.y), w2 = pack2(wa.z), w3 = pack2(wa.w);
#pragma unroll
        for (int bp = 0; bp < 16; bp++) {
            const ull h = hs2[bp][kk];
            ffma2(acc[bp][0], w0, h);
            ffma2(acc[bp][1], w1, h);
            ffma2(acc[bp][2], w2, h);
            ffma2(acc[bp][3], w3, h);
        }
        wa = wb; wb = wn;
    }

#pragma unroll
    for (int bp = 0; bp < 16; bp++) {
#pragma unroll
        for (int c = 0; c < 4; c++) {
            float2 v = unpack2(acc[bp][c]);
            g_qkv_part[blockIdx.y][2 * bp][col0 + c]     = v.x;
            g_qkv_part[blockIdx.y][2 * bp + 1][col0 + c] = v.y;
        }
    }
}

// ---------------- Kernel 2: split-K reduce + RoPE ----------------
// grid (B, 96): 0..31 q heads, 32..63 k heads, 64..95 v heads. 64 threads;
// thread d handles the rotary pair (d, d+64).
__global__ __launch_bounds__(64) void rope_kernel(const int* __restrict__ hist) {
    const int b = blockIdx.x, head = blockIdx.y, d = threadIdx.x;

    int col;
    if (head < 32)      col = head * DD + d;
    else if (head < 64) col = HID + (head - 32) * DD + d;
    else                col = 2 * HID + (head - 64) * DD + d;

    float x1 = 0.f, x2 = 0.f;
#pragma unroll
    for (int s = 0; s < KSPLIT_Q; s++) {
        x1 += g_qkv_part[s][b][col];
        x2 += g_qkv_part[s][b][col + 64];
    }

    float lo, hi;
    if (head < 64) {
        const float pos = (float)hist[b];
        const float inv = exp2f(-(float)(2 * d) * (13.287712379549449f / 128.f));
        const float ang = pos * inv;
        const float c = cosf(ang), sn = sinf(ang);
        lo = x1 * c - x2 * sn;
        hi = x2 * c + x1 * sn;
    } else {
        lo = x1; hi = x2;
    }

    if (head < 32) {
        g_q[(b * HH + head) * DD + d]      = lo;
        g_q[(b * HH + head) * DD + d + 64] = hi;
    } else if (head < 64) {
        const int h = head - 32;
        g_kn[(b * HH + h) * DD + d]      = lo;
        g_kn[(b * HH + h) * DD + d + 64] = hi;
    } else {
        const int h = head - 64;
        g_vn[(b * HH + h) * DD + d]      = lo;
        g_vn[(b * HH + h) * DD + d + 64] = hi;
    }
}

// ---------------- Kernel 3: paged decode attention ----------------
// 1 block per (b,h), 8 warps; warp w handles s = w, w+8, ...
// s == hist[b] served from g_kn/g_vn so input caches stay const.
__global__ __launch_bounds__(256) void attn_kernel(const float* __restrict__ kcache,
                                                   const float* __restrict__ vcache,
                                                   const int* __restrict__ hist,
                                                   const int* __restrict__ bo) {
    const int b = blockIdx.x, h = blockIdx.y;
    const int tid = threadIdx.x, w = tid >> 5, lane = tid & 31;

    __shared__ float sm_m[8], sm_l[8];
    __shared__ float sm_acc[8][DD];
    __shared__ int   sm_blk[NBLK];

    if (tid < NBLK) sm_blk[tid] = bo[b * NBLK + tid];
    const float4 q4 = reinterpret_cast<const float4*>(g_q + (size_t)(b * HH + h) * DD)[lane];
    const int n = hist[b] + 1;
    __syncthreads();

    float m = -1e30f, l = 0.f;
    float4 acc = make_float4(0.f, 0.f, 0.f, 0.f);

    for (int s = w; s < n; s += 8) {
        const float4 *kp, *vp;
        if (s == n - 1) {
            kp = reinterpret_cast<const float4*>(g_kn + (size_t)(b * HH + h) * DD);
            vp = reinterpret_cast<const float4*>(g_vn + (size_t)(b * HH + h) * DD);
        } else {
            const size_t base = ((((size_t)sm_blk[s >> 6]) * BSZ + (s & 63)) * HH + h) * DD;
            kp = reinterpret_cast<const float4*>(kcache + base);
            vp = reinterpret_cast<const float4*>(vcache + base);
        }
        const float4 kv = kp[lane];
        float dsum = q4.x * kv.x + q4.y * kv.y + q4.z * kv.z + q4.w * kv.w;
#pragma unroll
        for (int o = 16; o; o >>= 1) dsum += __shfl_xor_sync(0xffffffffu, dsum, o);
        const float score = dsum * 0.08838834764831845f;  // 1/sqrt(128)

        const float4 vv = vp[lane];
        const float mn = fmaxf(m, score);
        const float cf = __expf(m - mn);
        const float p  = __expf(score - mn);
        l = l * cf + p;
        acc.x = acc.x * cf + p * vv.x;
        acc.y = acc.y * cf + p * vv.y;
        acc.z = acc.z * cf + p * vv.z;
        acc.w = acc.w * cf + p * vv.w;
        m = mn;
    }

    if (lane == 0) { sm_m[w] = m; sm_l[w] = l; }
    reinterpret_cast<float4*>(sm_acc[w])[lane] = acc;
    __syncthreads();

    if (tid < DD) {
        float M = -1e30f;
#pragma unroll
        for (int i = 0; i < 8; i++) M = fmaxf(M, sm_m[i]);
        float L = 0.f, o = 0.f;
#pragma unroll
        for (int i = 0; i < 8; i++) {
            const float f = __expf(sm_m[i] - M);
            L += f * sm_l[i];
            o += f * sm_acc[i][tid];
        }
        g_attn[b * HID + h * DD + tid] = o / L;
    }
}

// ---------------- Kernel 4: output projection, split-K x4 ----------------
// grid (256 colblocks, 4 ksplits), 256 threads. Warp owns 2 columns, lanes
// split the 1024-wide k-range; batches packed f32x2. Coalesced Wo reads.
__global__ __launch_bounds__(256) void oproj_kernel(const float* __restrict__ Wo) {
    const int tid = threadIdx.x, w = tid >> 5, lane = tid & 31;
    const int j0 = blockIdx.x * 16 + w * 2;
    const int kbase = blockIdx.y * (HID / KSPLIT_O);   // 1024-wide slice

    __shared__ ull a2[16][256];

    ull acc[2][16];
#pragma unroll
    for (int jj = 0; jj < 2; jj++)
#pragma unroll
        for (int i = 0; i < 16; i++) acc[jj][i] = 0ull;

    for (int k0 = kbase; k0 < kbase + HID / KSPLIT_O; k0 += 256) {
        __syncthreads();
#pragma unroll
        for (int j = 0; j < 16; j++)
            a2[j][tid] = pack2(g_attn[(2 * j) * HID + k0 + tid],
                               g_attn[(2 * j + 1) * HID + k0 + tid]);
        __syncthreads();

        for (int kk = lane; kk < 256; kk += 32) {
            ull hv[16];
#pragma unroll
            for (int b2 = 0; b2 < 16; b2++) hv[b2] = a2[b2][kk];
#pragma unroll
            for (int jj = 0; jj < 2; jj++) {
                const ull w2 = pack2(Wo[(size_t)(j0 + jj) * HID + k0 + kk]);
#pragma unroll
                for (int b2 = 0; b2 < 16; b2++) ffma2(acc[jj][b2], w2, hv[b2]);
            }
        }
    }

#pragma unroll
    for (int jj = 0; jj < 2; jj++) {
#pragma unroll
        for (int b2 = 0; b2 < 16; b2++) {
            float2 v = unpack2(acc[jj][b2]);
#pragma unroll
            for (int o = 16; o; o >>= 1) {
                v.x += __shfl_xor_sync(0xffffffffu, v.x, o);
                v.y += __shfl_xor_sync(0xffffffffu, v.y, o);
            }
            if (lane == 0) {
                g_o_part[blockIdx.y][2 * b2][j0 + jj]     = v.x;
                g_o_part[blockIdx.y][2 * b2 + 1][j0 + jj] = v.y;
            }
        }
    }
}

// ---------------- Kernel 5: oproj split-K reduce ----------------
__global__ __launch_bounds__(256) void oreduce_kernel(float* __restrict__ out) {
    const int i = blockIdx.x * 256 + threadIdx.x;   // over 32*4096
    const int b = i >> 12, j = i & (HID - 1);
    float s = 0.f;
#pragma unroll
    for (int sp = 0; sp < KSPLIT_O; sp++) s += g_o_part[sp][b][j];
    out[i] = s;
}

// ---------------- launch ----------------
extern "C" void kernel_launch(void* const* d_in, const int* in_sizes, int n_in,
                              void* d_out, int out_size) {
    const float* hs     = (const float*)d_in[0];
    const float* Wpack  = (const float*)d_in[1];
    const float* Wo     = (const float*)d_in[2];
    const float* kcache = (const float*)d_in[3];
    const float* vcache = (const float*)d_in[4];
    const int*   hist   = (const int*)d_in[5];
    const int*   bo     = (const int*)d_in[6];
    float* out = (float*)d_out;

    qkv_kernel   <<<dim3(24, KSPLIT_Q), 128>>>(hs, Wpack);
    rope_kernel  <<<dim3(BB, 96), 64>>>(hist);
    attn_kernel  <<<dim3(BB, HH), 256>>>(kcache, vcache, hist, bo);
    oproj_kernel <<<dim3(256, KSPLIT_O), 256>>>(Wo);
    oreduce_kernel<<<(BB * HID) / 256, 256>>>(out);
}